// round 1
// baseline (speedup 1.0000x reference)
#include <cuda_runtime.h>

// IdentityResBlock: x[200000,256] -> GEMM1 -> BN -> ReLU -> 27-neigh gather GEMM -> BN -> ReLU
//                   -> GEMM3 -> BN -> +x -> ReLU
// Training-mode BN: batch stats over the node dim, fused into each GEMM epilogue.

#define N_NODES 200000
#define NTILES  3125          // 200000 / 64, exact
#define EPS_BN  1e-3f

// ---- scratch (device globals; allocation-free per harness rules) ----
__device__ __align__(16) float g_y1[N_NODES * 64];           // raw GEMM1 out
__device__ __align__(16) float g_h1[N_NODES * 64];           // BN1+ReLU
__device__ __align__(16) float g_y2[N_NODES * 64];           // raw GEMM2 out
__device__ __align__(16) float g_h2[N_NODES * 64];           // BN2+ReLU
__device__ __align__(16) float g_y3[(size_t)N_NODES * 256];  // raw GEMM3 out
// layout: [s1(64) ss1(64) s2(64) ss2(64) s3(256) ss3(256)]
__device__ __align__(16) float g_s[768];
// layout: [a1(64) b1(64) a2(64) b2(64) a3(256) b3(256)]
__device__ __align__(16) float g_ab[768];

__global__ void k_init_stats() {
    int t = threadIdx.x;
    if (t < 768) g_s[t] = 0.0f;
}

// 4x4 register-tiled inner product over one 64-wide K chunk.
// hs: [64 nodes][68 pad]  (pad 68 => bank = (4n + c) % 32, conflict-free broadcast reads)
// ws: [64 c][64 d]        (float4 reads of consecutive d, conflict-light)
__device__ __forceinline__ void mm_inner(const float (*hs)[68], const float (*ws)[64],
                                         int ng4, int dg4, float acc[4][4]) {
#pragma unroll 16
    for (int c = 0; c < 64; ++c) {
        float4 w = *(const float4*)&ws[c][dg4];
        float h0 = hs[ng4 + 0][c];
        float h1 = hs[ng4 + 1][c];
        float h2 = hs[ng4 + 2][c];
        float h3 = hs[ng4 + 3][c];
        acc[0][0] = fmaf(h0, w.x, acc[0][0]); acc[0][1] = fmaf(h0, w.y, acc[0][1]);
        acc[0][2] = fmaf(h0, w.z, acc[0][2]); acc[0][3] = fmaf(h0, w.w, acc[0][3]);
        acc[1][0] = fmaf(h1, w.x, acc[1][0]); acc[1][1] = fmaf(h1, w.y, acc[1][1]);
        acc[1][2] = fmaf(h1, w.z, acc[1][2]); acc[1][3] = fmaf(h1, w.w, acc[1][3]);
        acc[2][0] = fmaf(h2, w.x, acc[2][0]); acc[2][1] = fmaf(h2, w.y, acc[2][1]);
        acc[2][2] = fmaf(h2, w.z, acc[2][2]); acc[2][3] = fmaf(h2, w.w, acc[2][3]);
        acc[3][0] = fmaf(h3, w.x, acc[3][0]); acc[3][1] = fmaf(h3, w.y, acc[3][1]);
        acc[3][2] = fmaf(h3, w.z, acc[3][2]); acc[3][3] = fmaf(h3, w.w, acc[3][3]);
    }
}

// ---- GEMM1: y1 = x @ W1   ([N,256] @ [256,64]) + fused column sum/sumsq ----
__global__ __launch_bounds__(256, 2) void k_gemm1(const float* __restrict__ x,
                                                  const float* __restrict__ W1) {
    __shared__ float hs[64][68];
    __shared__ float ws[64][64];
    __shared__ float csum[64], csq[64];

    int tid = threadIdx.x;
    int n0  = blockIdx.x * 64;
    int dg4 = (tid & 15) * 4;
    int ng4 = (tid >> 4) * 4;
    int c4  = tid & 15;
    int r0  = tid >> 4;

    if (tid < 64) { csum[tid] = 0.0f; csq[tid] = 0.0f; }

    float acc[4][4];
#pragma unroll
    for (int i = 0; i < 4; ++i)
#pragma unroll
        for (int j = 0; j < 4; ++j) acc[i][j] = 0.0f;

    for (int kc = 0; kc < 4; ++kc) {
#pragma unroll
        for (int it = 0; it < 4; ++it) {
            int r = r0 + it * 16;
            *(float4*)&hs[r][c4 * 4] =
                *(const float4*)&x[(size_t)(n0 + r) * 256 + kc * 64 + c4 * 4];
            *(float4*)&ws[r][c4 * 4] =
                *(const float4*)&W1[(size_t)(kc * 64 + r) * 64 + c4 * 4];
        }
        __syncthreads();
        mm_inner(hs, ws, ng4, dg4, acc);
        __syncthreads();
    }

#pragma unroll
    for (int i = 0; i < 4; ++i)
        *(float4*)&g_y1[(size_t)(n0 + ng4 + i) * 64 + dg4] =
            make_float4(acc[i][0], acc[i][1], acc[i][2], acc[i][3]);

#pragma unroll
    for (int j = 0; j < 4; ++j) {
        float s = 0.0f, q = 0.0f;
#pragma unroll
        for (int i = 0; i < 4; ++i) { float v = acc[i][j]; s += v; q += v * v; }
        atomicAdd(&csum[dg4 + j], s);
        atomicAdd(&csq[dg4 + j], q);
    }
    __syncthreads();
    if (tid < 64) {
        atomicAdd(&g_s[0  + tid], csum[tid]);
        atomicAdd(&g_s[64 + tid], csq[tid]);
    }
}

// ---- prep BN affine: a = gamma*rsqrt(var+eps), b = beta - mean*a ----
__global__ void k_prep(const float* __restrict__ gamma, const float* __restrict__ beta,
                       int sIdx, int abIdx, int C) {
    int t = threadIdx.x;
    if (t < C) {
        float invN = 1.0f / (float)N_NODES;
        float mean = g_s[sIdx + t] * invN;
        float var  = g_s[sIdx + C + t] * invN - mean * mean;
        float a    = gamma[t] * rsqrtf(var + EPS_BN);
        g_ab[abIdx + t]     = a;
        g_ab[abIdx + C + t] = beta[t] - mean * a;
    }
}

// ---- BN apply + ReLU for 64-wide intermediates ----
__global__ void k_bnapply(int which) {
    const float* y = which ? g_y2 : g_y1;
    float*       h = which ? g_h2 : g_h1;
    int ab = which ? 128 : 0;
    size_t base = ((size_t)blockIdx.x * blockDim.x + threadIdx.x) * 4;
    int d = (int)(base & 63);
    float4 yv = *(const float4*)&y[base];
    float4 a  = *(const float4*)&g_ab[ab + d];
    float4 b  = *(const float4*)&g_ab[ab + 64 + d];
    float4 o;
    o.x = fmaxf(fmaf(yv.x, a.x, b.x), 0.0f);
    o.y = fmaxf(fmaf(yv.y, a.y, b.y), 0.0f);
    o.z = fmaxf(fmaf(yv.z, a.z, b.z), 0.0f);
    o.w = fmaxf(fmaf(yv.w, a.w, b.w), 0.0f);
    *(float4*)&h[base] = o;
}

// ---- GEMM2: y2[n,d] = sum_k sum_c h1[neigh[n,k],c] * W2[k,c,d]  + fused stats ----
__global__ __launch_bounds__(256, 2) void k_gemm2(const int* __restrict__ neigh,
                                                  const float* __restrict__ W2) {
    __shared__ float hs[64][68];
    __shared__ float ws[64][64];
    __shared__ int   ns[27 * 64];
    __shared__ float csum[64], csq[64];

    int tid = threadIdx.x;
    int n0  = blockIdx.x * 64;
    int dg4 = (tid & 15) * 4;
    int ng4 = (tid >> 4) * 4;
    int c4  = tid & 15;
    int r0  = tid >> 4;

    if (tid < 64) { csum[tid] = 0.0f; csq[tid] = 0.0f; }

    // neigh tile, transposed to [k][n] for broadcast-friendly reads
    for (int i = tid; i < 27 * 64; i += 256) {
        int n = i / 27;
        int k = i - n * 27;
        ns[k * 64 + n] = neigh[(size_t)n0 * 27 + i];
    }

    float acc[4][4];
#pragma unroll
    for (int i = 0; i < 4; ++i)
#pragma unroll
        for (int j = 0; j < 4; ++j) acc[i][j] = 0.0f;

    __syncthreads();

    for (int k = 0; k < 27; ++k) {
#pragma unroll
        for (int it = 0; it < 4; ++it) {
            int r   = r0 + it * 16;
            int row = ns[k * 64 + r];
            *(float4*)&hs[r][c4 * 4] =
                *(const float4*)&g_h1[(size_t)row * 64 + c4 * 4];     // L2-resident gather
            *(float4*)&ws[r][c4 * 4] =
                *(const float4*)&W2[(size_t)k * 4096 + r * 64 + c4 * 4];
        }
        __syncthreads();
        mm_inner(hs, ws, ng4, dg4, acc);
        __syncthreads();
    }

#pragma unroll
    for (int i = 0; i < 4; ++i)
        *(float4*)&g_y2[(size_t)(n0 + ng4 + i) * 64 + dg4] =
            make_float4(acc[i][0], acc[i][1], acc[i][2], acc[i][3]);

#pragma unroll
    for (int j = 0; j < 4; ++j) {
        float s = 0.0f, q = 0.0f;
#pragma unroll
        for (int i = 0; i < 4; ++i) { float v = acc[i][j]; s += v; q += v * v; }
        atomicAdd(&csum[dg4 + j], s);
        atomicAdd(&csq[dg4 + j], q);
    }
    __syncthreads();
    if (tid < 64) {
        atomicAdd(&g_s[128 + tid], csum[tid]);
        atomicAdd(&g_s[192 + tid], csq[tid]);
    }
}

// ---- GEMM3: y3 = h2 @ W3   ([N,64] @ [64,256]) + fused stats ----
__global__ __launch_bounds__(256, 2) void k_gemm3(const float* __restrict__ W3) {
    __shared__ float hs[64][68];
    __shared__ float ws[64][64];
    __shared__ float csum[64], csq[64];

    int tid = threadIdx.x;
    int n0  = blockIdx.x * 64;
    int db  = blockIdx.y * 64;     // output-column chunk
    int dg4 = (tid & 15) * 4;
    int ng4 = (tid >> 4) * 4;
    int c4  = tid & 15;
    int r0  = tid >> 4;

    if (tid < 64) { csum[tid] = 0.0f; csq[tid] = 0.0f; }

    float acc[4][4];
#pragma unroll
    for (int i = 0; i < 4; ++i)
#pragma unroll
        for (int j = 0; j < 4; ++j) acc[i][j] = 0.0f;

#pragma unroll
    for (int it = 0; it < 4; ++it) {
        int r = r0 + it * 16;
        *(float4*)&hs[r][c4 * 4] =
            *(const float4*)&g_h2[(size_t)(n0 + r) * 64 + c4 * 4];
        *(float4*)&ws[r][c4 * 4] =
            *(const float4*)&W3[(size_t)r * 256 + db + c4 * 4];
    }
    __syncthreads();
    mm_inner(hs, ws, ng4, dg4, acc);
    __syncthreads();

#pragma unroll
    for (int i = 0; i < 4; ++i)
        *(float4*)&g_y3[(size_t)(n0 + ng4 + i) * 256 + db + dg4] =
            make_float4(acc[i][0], acc[i][1], acc[i][2], acc[i][3]);

#pragma unroll
    for (int j = 0; j < 4; ++j) {
        float s = 0.0f, q = 0.0f;
#pragma unroll
        for (int i = 0; i < 4; ++i) { float v = acc[i][j]; s += v; q += v * v; }
        atomicAdd(&csum[dg4 + j], s);
        atomicAdd(&csq[dg4 + j], q);
    }
    __syncthreads();
    if (tid < 64) {
        atomicAdd(&g_s[256 + db + tid], csum[tid]);
        atomicAdd(&g_s[512 + db + tid], csq[tid]);
    }
}

// ---- final: out = relu(BN3(y3) + x) ----
__global__ void k_final(const float* __restrict__ x, float* __restrict__ out) {
    size_t base = ((size_t)blockIdx.x * 256 + threadIdx.x) * 4;
    int d = (int)(base & 255);
    float4 yv = *(const float4*)&g_y3[base];
    float4 a  = *(const float4*)&g_ab[256 + d];
    float4 b  = *(const float4*)&g_ab[512 + d];
    float4 xv = *(const float4*)&x[base];
    float4 o;
    o.x = fmaxf(fmaf(yv.x, a.x, b.x) + xv.x, 0.0f);
    o.y = fmaxf(fmaf(yv.y, a.y, b.y) + xv.y, 0.0f);
    o.z = fmaxf(fmaf(yv.z, a.z, b.z) + xv.z, 0.0f);
    o.w = fmaxf(fmaf(yv.w, a.w, b.w) + xv.w, 0.0f);
    *(float4*)&out[base] = o;
}

extern "C" void kernel_launch(void* const* d_in, const int* in_sizes, int n_in,
                              void* d_out, int out_size) {
    const float* x     = (const float*)d_in[0];
    const int*   neigh = (const int*)  d_in[1];
    // d_in[2] = depth (unused)
    const float* W1 = (const float*)d_in[3];
    const float* g1 = (const float*)d_in[4];
    const float* b1 = (const float*)d_in[5];
    const float* W2 = (const float*)d_in[6];
    const float* g2 = (const float*)d_in[7];
    const float* b2 = (const float*)d_in[8];
    const float* W3 = (const float*)d_in[9];
    const float* g3 = (const float*)d_in[10];
    const float* b3 = (const float*)d_in[11];
    float* out = (float*)d_out;

    k_init_stats<<<1, 768>>>();

    k_gemm1<<<NTILES, 256>>>(x, W1);
    k_prep<<<1, 64>>>(g1, b1, /*sIdx=*/0, /*abIdx=*/0, 64);
    k_bnapply<<<12500, 256>>>(0);                 // 12500*256*4 = N*64

    k_gemm2<<<NTILES, 256>>>(neigh, W2);
    k_prep<<<1, 64>>>(g2, b2, /*sIdx=*/128, /*abIdx=*/128, 64);
    k_bnapply<<<12500, 256>>>(1);

    k_gemm3<<<dim3(NTILES, 4), 256>>>(W3);
    k_prep<<<1, 256>>>(g3, b3, /*sIdx=*/256, /*abIdx=*/256, 256);
    k_final<<<50000, 256>>>(x, out);              // 50000*256*4 = N*256
}